// round 1
// baseline (speedup 1.0000x reference)
#include <cuda_runtime.h>

// ---------------- problem dims (fixed by the dataset) ----------------
#define BATCH   2
#define C_IN    256
#define HH      40
#define WW      40
#define CMID    64     // compressed channels
#define CK      100    // k2 * S^2 encoder output channels
#define KK      25     // k2
#define HPAD    44     // xT padded (halo 2)
#define CPH     42     // comp padded (halo 1)

// ---------------- scratch (zero-initialized at module load; halos stay 0) ----------------
__device__ float g_xT  [BATCH * HPAD * HPAD * C_IN];   // x NHWC, 2-px zero halo (~3.96 MB)
__device__ float g_comp[BATCH * CPH  * CPH  * CMID];   // compressed NHWC, 1-px zero halo
__device__ float g_kern[BATCH * HH * WW * CK];         // encoder conv out, NHWC
__device__ float g_wt  [9 * CMID * CK];                // w_enc transposed [tap][ci][o]

// ---------------- stage 0: transpose w_enc (100,64,3,3) -> [tap][ci][o] ----------------
__global__ void wenc_transpose_kernel(const float* __restrict__ wenc) {
    int i = blockIdx.x * 256 + threadIdx.x;
    if (i >= 9 * CMID * CK) return;
    int tap  = i / (CMID * CK);
    int rest = i % (CMID * CK);
    int ci   = rest / CK;
    int o    = rest % CK;
    g_wt[i] = wenc[o * (CMID * 9) + ci * 9 + tap];
}

// ---------------- stage A: 1x1 compress GEMM + fused x transpose ----------------
// grid = BATCH*50 blocks, 256 threads. Each block: 32 pixels x 64 outputs.
// dynamic smem: w_s[256][68] + x_s[64][33]
#define WS_STRIDE 68
#define XS_STRIDE 33
#define SMEM_A_BYTES ((C_IN * WS_STRIDE + 64 * XS_STRIDE) * (int)sizeof(float))

__global__ void stageA_compress(const float* __restrict__ x,
                                const float* __restrict__ wcomp) {
    extern __shared__ float sm[];
    float* w_s = sm;                       // [c][o] padded stride 68
    float* x_s = sm + C_IN * WS_STRIDE;    // [c_l][pix] padded stride 33

    const int t    = threadIdx.x;
    const int blk  = blockIdx.x;
    const int b    = blk / 50;
    const int pix0 = (blk % 50) * 32;

    // load all of w_comp (64 x 256), transposed to [c][o]
    for (int i = t; i < CMID * C_IN; i += 256) {
        int o = i >> 8, c = i & 255;
        w_s[c * WS_STRIDE + o] = wcomp[i];
    }

    float acc[8] = {0.f, 0.f, 0.f, 0.f, 0.f, 0.f, 0.f, 0.f};
    const int pix_l = t & 31;
    const int o0    = (t >> 5) << 3;       // 8 consecutive output channels

    for (int c0 = 0; c0 < C_IN; c0 += 64) {
        __syncthreads();
        // load x chunk [64 c][32 pix], coalesced along pixels
        #pragma unroll
        for (int r = 0; r < 8; r++) {
            int idx = t + r * 256;
            int cl = idx >> 5, pl = idx & 31;
            x_s[cl * XS_STRIDE + pl] =
                x[(size_t)(b * C_IN + c0 + cl) * (HH * WW) + pix0 + pl];
        }
        __syncthreads();
        // emit transposed x to g_xT (coalesced along channels)
        #pragma unroll
        for (int r = 0; r < 8; r++) {
            int idx = t + r * 256;
            int cl = idx & 63, pl = idx >> 6;
            int pix = pix0 + pl;
            int hs = pix / WW, ws = pix % WW;
            g_xT[((size_t)(b * HPAD + hs + 2) * HPAD + (ws + 2)) * C_IN + c0 + cl] =
                x_s[cl * XS_STRIDE + pl];
        }
        // GEMM chunk
        #pragma unroll 16
        for (int c = 0; c < 64; c++) {
            float xv = x_s[c * XS_STRIDE + pix_l];
            const float4 w0 = *(const float4*)&w_s[(c0 + c) * WS_STRIDE + o0];
            const float4 w1 = *(const float4*)&w_s[(c0 + c) * WS_STRIDE + o0 + 4];
            acc[0] += xv * w0.x; acc[1] += xv * w0.y;
            acc[2] += xv * w0.z; acc[3] += xv * w0.w;
            acc[4] += xv * w1.x; acc[5] += xv * w1.y;
            acc[6] += xv * w1.z; acc[7] += xv * w1.w;
        }
    }

    const int pix = pix0 + pix_l;
    const int hs = pix / WW, ws = pix % WW;
    float* dst = &g_comp[((size_t)(b * CPH + hs + 1) * CPH + (ws + 1)) * CMID + o0];
    *(float4*)(dst)     = make_float4(acc[0], acc[1], acc[2], acc[3]);
    *(float4*)(dst + 4) = make_float4(acc[4], acc[5], acc[6], acc[7]);
}

// ---------------- stage B: 3x3 encoder conv (64 -> 100 ch) ----------------
// grid = BATCH*40*4 = 320 blocks, 256 threads (250 compute: 10 pixels x 25 o-groups of 4)
__global__ void stageB_encoder() {
    __shared__ float comp_s[3 * 12 * CMID];   // rows h..h+2, cols ws0..ws0+11
    __shared__ float w_s[CMID * CK];          // one tap slice [ci][o]

    const int t   = threadIdx.x;
    const int blk = blockIdx.x;
    const int b   = blk / 160;
    const int rem = blk % 160;
    const int h   = rem >> 2;
    const int ws0 = (rem & 3) * 10;

    // comp tile (padded coords, contiguous rows)
    for (int i = t; i < 3 * 12 * CMID; i += 256) {
        int row  = i / (12 * CMID);
        int rest = i % (12 * CMID);
        comp_s[i] = g_comp[((size_t)(b * CPH + h + row) * CPH + ws0) * CMID + rest];
    }

    const int pixg = t / 25;   // 0..9
    const int og   = t % 25;   // 4 consecutive outputs
    float a0 = 0.f, a1 = 0.f, a2 = 0.f, a3 = 0.f;

    for (int tap = 0; tap < 9; tap++) {
        __syncthreads();
        for (int i = t; i < CMID * CK; i += 256)
            w_s[i] = g_wt[tap * (CMID * CK) + i];
        __syncthreads();
        if (t < 250) {
            const int dh = tap / 3, dw = tap % 3;
            const float* cp = &comp_s[(dh * 12 + pixg + dw) * CMID];
            #pragma unroll 16
            for (int ci = 0; ci < CMID; ci++) {
                float v = cp[ci];
                const float4 w = *(const float4*)&w_s[ci * CK + og * 4];
                a0 += v * w.x; a1 += v * w.y; a2 += v * w.z; a3 += v * w.w;
            }
        }
    }
    if (t < 250) {
        float* dst = &g_kern[((size_t)(b * HH + h) * WW + ws0 + pixg) * CK + og * 4];
        *(float4*)dst = make_float4(a0, a1, a2, a3);
    }
}

// ---------------- stage C: pixel-shuffle + softmax + reassembly ----------------
// grid = BATCH*1600 blocks (one per source pixel p), 256 threads (one per channel).
__global__ void stageC_reassemble(float* __restrict__ out) {
    __shared__ float4 sk[KK];   // sk[k] = softmax weights for d = 0..3

    const int t   = threadIdx.x;
    const int blk = blockIdx.x;
    const int b   = blk / (HH * WW);
    const int p   = blk % (HH * WW);

    const int hsrc = p / WW, wsrc = p % WW;
    const int hu   = p / 20;
    const int pm20 = p % 20;
    const int wu0  = pm20 * 4;
    const int hc   = hu >> 1;
    const int sh   = hu & 1;
    const int wc0  = pm20 * 2;

    const int wid = t >> 5, lane = t & 31;
    if (wid < 4) {
        // d = wid: kern pixel (hc, wc0 + d/2), channel = k*4 + sh*2 + d%2
        float v = -3.0e38f;
        if (lane < KK)
            v = g_kern[((size_t)(b * HH + hc) * WW + wc0 + (wid >> 1)) * CK
                       + lane * 4 + sh * 2 + (wid & 1)];
        float m = v;
        #pragma unroll
        for (int off = 16; off; off >>= 1)
            m = fmaxf(m, __shfl_xor_sync(0xffffffffu, m, off));
        float e = (lane < KK) ? __expf(v - m) : 0.f;
        float s = e;
        #pragma unroll
        for (int off = 16; off; off >>= 1)
            s += __shfl_xor_sync(0xffffffffu, s, off);
        if (lane < KK)
            ((float*)&sk[lane])[wid] = e / s;
    }
    __syncthreads();

    // per-channel dot over the 5x5 patch (padded NHWC -> no bounds checks)
    const float* xb = &g_xT[((size_t)(b * HPAD + hsrc) * HPAD + wsrc) * C_IN + t];
    float4 acc = make_float4(0.f, 0.f, 0.f, 0.f);
    #pragma unroll
    for (int ki = 0; ki < 5; ki++) {
        #pragma unroll
        for (int kj = 0; kj < 5; kj++) {
            float xv = xb[(ki * HPAD + kj) * C_IN];
            const float4 w = sk[ki * 5 + kj];
            acc.x += xv * w.x; acc.y += xv * w.y;
            acc.z += xv * w.z; acc.w += xv * w.w;
        }
    }
    // output NCHW; the 4 sub-pixels (hu, wu0..wu0+3) are contiguous
    float* dst = out + ((size_t)(b * C_IN + t) * (2 * HH) + hu) * (2 * WW) + wu0;
    *(float4*)dst = acc;
}

// ---------------- launch ----------------
extern "C" void kernel_launch(void* const* d_in, const int* in_sizes, int n_in,
                              void* d_out, int out_size) {
    const float* x     = (const float*)d_in[0];
    const float* wcomp = (const float*)d_in[1];
    const float* wenc  = (const float*)d_in[2];
    float* out = (float*)d_out;

    cudaFuncSetAttribute(stageA_compress,
                         cudaFuncAttributeMaxDynamicSharedMemorySize, SMEM_A_BYTES);

    wenc_transpose_kernel<<<(9 * CMID * CK + 255) / 256, 256>>>(wenc);
    stageA_compress<<<BATCH * 50, 256, SMEM_A_BYTES>>>(x, wcomp);
    stageB_encoder<<<BATCH * 40 * 4, 256>>>();
    stageC_reassemble<<<BATCH * HH * WW, 256>>>(out);
}

// round 2
// speedup vs baseline: 1.5377x; 1.5377x over previous
#include <cuda_runtime.h>
#include <cuda_pipeline.h>

// ---------------- problem dims (fixed by the dataset) ----------------
#define BATCH   2
#define C_IN    256
#define HH      40
#define WW      40
#define CMID    64     // compressed channels
#define CK      100    // k2 * S^2 encoder output channels
#define KK      25     // k2
#define HPAD    44     // xT padded (halo 2)
#define CPH     42     // comp padded (halo 1)

typedef unsigned long long u64;

__device__ __forceinline__ u64 dup2f(float x) {
    u64 r; asm("mov.b64 %0,{%1,%1};" : "=l"(r) : "f"(x)); return r;
}
__device__ __forceinline__ void fma2(u64& d, u64 a, u64 b) {
    asm("fma.rn.f32x2 %0,%1,%2,%0;" : "+l"(d) : "l"(a), "l"(b));
}

// ---------------- scratch (zero-initialized at module load; halos stay 0) ----------------
__device__ __align__(16) float g_xT  [BATCH * HPAD * HPAD * C_IN];   // x NHWC, 2-px zero halo
__device__ __align__(16) float g_comp[BATCH * CPH  * CPH  * CMID];   // compressed NHWC, 1-px halo
__device__ __align__(16) float g_kern[BATCH * HH * WW * CK];         // encoder conv out, NHWC
__device__ __align__(16) float g_wt  [9 * CMID * CK];                // w_enc transposed [tap][ci][o]

// ---------------- stage A: 1x1 compress GEMM + fused x transpose + wenc transpose ----------------
// blocks 0..99: GEMM (32 pixels x 64 outputs each). blocks 100..324: wenc transpose.
#define WS_STRIDE 68
#define XS_STRIDE 33
#define SMEM_A_BYTES ((C_IN * WS_STRIDE + 64 * XS_STRIDE) * (int)sizeof(float))

__global__ void stageA_compress(const float* __restrict__ x,
                                const float* __restrict__ wcomp,
                                const float* __restrict__ wenc) {
    extern __shared__ float sm[];
    float* w_s = sm;                       // [c][o] padded stride 68
    float* x_s = sm + C_IN * WS_STRIDE;    // [c_l][pix] padded stride 33

    const int t   = threadIdx.x;
    const int blk = blockIdx.x;

    if (blk >= 100) {                      // w_enc transpose: (100,64,3,3) -> [tap][ci][o]
        int i = (blk - 100) * 256 + t;
        if (i < 9 * CMID * CK) {
            int tap  = i / (CMID * CK);
            int rest = i % (CMID * CK);
            int ci   = rest / CK;
            int o    = rest % CK;
            g_wt[i] = wenc[o * (CMID * 9) + ci * 9 + tap];
        }
        return;
    }

    const int b    = blk / 50;
    const int pix0 = (blk % 50) * 32;

    // load all of w_comp (64 x 256), transposed to [c][o]
    for (int i = t; i < CMID * C_IN; i += 256) {
        int o = i >> 8, c = i & 255;
        w_s[c * WS_STRIDE + o] = wcomp[i];
    }

    u64 acc[4] = {0ull, 0ull, 0ull, 0ull};
    const int pix_l = t & 31;              // warp spans 32 pixels (x coalesced)
    const int o0    = (t >> 5) << 3;       // warp shares o0 (w broadcast)

    for (int c0 = 0; c0 < C_IN; c0 += 64) {
        __syncthreads();
        #pragma unroll
        for (int r = 0; r < 8; r++) {
            int idx = t + r * 256;
            int cl = idx >> 5, pl = idx & 31;
            x_s[cl * XS_STRIDE + pl] =
                x[(size_t)(b * C_IN + c0 + cl) * (HH * WW) + pix0 + pl];
        }
        __syncthreads();
        // emit transposed x to g_xT (coalesced along channels)
        #pragma unroll
        for (int r = 0; r < 8; r++) {
            int idx = t + r * 256;
            int cl = idx & 63, pl = idx >> 6;
            int pix = pix0 + pl;
            int hs = pix / WW, ws = pix % WW;
            g_xT[((size_t)(b * HPAD + hs + 2) * HPAD + (ws + 2)) * C_IN + c0 + cl] =
                x_s[cl * XS_STRIDE + pl];
        }
        #pragma unroll 16
        for (int c = 0; c < 64; c++) {
            float xv = x_s[c * XS_STRIDE + pix_l];
            u64 xx = dup2f(xv);
            ulonglong2 wa = *(const ulonglong2*)&w_s[(c0 + c) * WS_STRIDE + o0];
            ulonglong2 wb = *(const ulonglong2*)&w_s[(c0 + c) * WS_STRIDE + o0 + 4];
            fma2(acc[0], xx, wa.x); fma2(acc[1], xx, wa.y);
            fma2(acc[2], xx, wb.x); fma2(acc[3], xx, wb.y);
        }
    }

    const int pix = pix0 + pix_l;
    const int hs = pix / WW, ws = pix % WW;
    float* dst = &g_comp[((size_t)(b * CPH + hs + 1) * CPH + (ws + 1)) * CMID + o0];
    *(ulonglong2*)(dst)     = make_ulonglong2(acc[0], acc[1]);
    *(ulonglong2*)(dst + 4) = make_ulonglong2(acc[2], acc[3]);
}

// ---------------- stage B: 3x3 encoder conv (64 -> 100 ch) ----------------
// grid = 160 (b x 20 row-pairs x 4 col-segments of 10), 128 threads.
// Thread (og=t/5, pxg=t%5) computes 4 px (2 rows x cols {2pxg,2pxg+1}) x 4 outputs.
// Weights double-buffered via cp.async; x in smem with stride 66 (bank-clean LDS.64 ci-pairs).
#define CS_STRIDE 66
#define B_WBUF    (CMID * CK)                 // 6400 floats per tap
#define SMEM_B_BYTES ((2 * B_WBUF + 48 * CS_STRIDE) * (int)sizeof(float))

__global__ void __launch_bounds__(128) stageB_encoder() {
    extern __shared__ float smB[];
    float* wbuf   = smB;                       // [2][6400]
    float* comp_s = smB + 2 * B_WBUF;          // [48 px][66]

    const int t   = threadIdx.x;
    const int blk = blockIdx.x;
    const int b   = blk / 80;
    const int rem = blk % 80;
    const int h0  = (rem / 4) * 2;
    const int ws0 = (rem % 4) * 10;

    // comp tile: padded rows h0..h0+3, padded cols ws0..ws0+11
    for (int i = t; i < 48 * CMID; i += 128) {
        int pxl = i >> 6, ci = i & 63;
        comp_s[pxl * CS_STRIDE + ci] =
            g_comp[((size_t)(b * CPH + h0 + pxl / 12) * CPH + ws0 + pxl % 12) * CMID + ci];
    }

    // preload tap 0 weights
    for (int i = t; i < B_WBUF / 4; i += 128)
        __pipeline_memcpy_async(&wbuf[i * 4], &g_wt[i * 4], 16);
    __pipeline_commit();

    const int og  = t / 5;          // 0..24 (t<125 active)
    const int pxg = t % 5;
    const bool active = (t < 125);

    u64 a00 = 0, a01 = 0, a10 = 0, a11 = 0;   // row0 col0/col1: {o0,o1},{o2,o3} packed per px
    u64 b00 = 0, b01 = 0, b10 = 0, b11 = 0;   // row1

    for (int tap = 0; tap < 9; tap++) {
        if (tap < 8) {
            float* dst = &wbuf[((tap + 1) & 1) * B_WBUF];
            const float* src = &g_wt[(tap + 1) * B_WBUF];
            for (int i = t; i < B_WBUF / 4; i += 128)
                __pipeline_memcpy_async(&dst[i * 4], &src[i * 4], 16);
            __pipeline_commit();
            __pipeline_wait_prior(1);
        } else {
            __pipeline_wait_prior(0);
        }
        __syncthreads();

        if (active) {
            const float* ws = &wbuf[(tap & 1) * B_WBUF];
            const int dh = tap / 3, dw = tap % 3;
            const float* p00 = &comp_s[(dh * 12 + 2 * pxg + dw) * CS_STRIDE];
            const float* p01 = p00 + CS_STRIDE;
            const float* p10 = p00 + 12 * CS_STRIDE;
            const float* p11 = p10 + CS_STRIDE;
            #pragma unroll 8
            for (int ci = 0; ci < CMID; ci += 2) {
                float2 x00 = *(const float2*)&p00[ci];
                float2 x01 = *(const float2*)&p01[ci];
                float2 x10 = *(const float2*)&p10[ci];
                float2 x11 = *(const float2*)&p11[ci];
                ulonglong2 w0 = *(const ulonglong2*)&ws[ci * CK + og * 4];
                ulonglong2 w1 = *(const ulonglong2*)&ws[(ci + 1) * CK + og * 4];
                u64 d;
                d = dup2f(x00.x); fma2(a00, d, w0.x); fma2(a01, d, w0.y);
                d = dup2f(x01.x); fma2(a10, d, w0.x); fma2(a11, d, w0.y);
                d = dup2f(x10.x); fma2(b00, d, w0.x); fma2(b01, d, w0.y);
                d = dup2f(x11.x); fma2(b10, d, w0.x); fma2(b11, d, w0.y);
                d = dup2f(x00.y); fma2(a00, d, w1.x); fma2(a01, d, w1.y);
                d = dup2f(x01.y); fma2(a10, d, w1.x); fma2(a11, d, w1.y);
                d = dup2f(x10.y); fma2(b00, d, w1.x); fma2(b01, d, w1.y);
                d = dup2f(x11.y); fma2(b10, d, w1.x); fma2(b11, d, w1.y);
            }
        }
        __syncthreads();
    }

    if (active) {
        const int c0 = ws0 + 2 * pxg;
        float* r0 = &g_kern[((size_t)(b * HH + h0) * WW + c0) * CK + og * 4];
        float* r1 = &g_kern[((size_t)(b * HH + h0 + 1) * WW + c0) * CK + og * 4];
        *(ulonglong2*)(r0)      = make_ulonglong2(a00, a01);
        *(ulonglong2*)(r0 + CK) = make_ulonglong2(a10, a11);
        *(ulonglong2*)(r1)      = make_ulonglong2(b00, b01);
        *(ulonglong2*)(r1 + CK) = make_ulonglong2(b10, b11);
    }
}

// ---------------- stage C: pixel-shuffle + softmax + reassembly ----------------
// grid = BATCH*800 blocks (2 src pixels each), 256 threads (2 channels each).
__global__ void __launch_bounds__(256, 2) stageC_reassemble(float* __restrict__ out) {
    __shared__ float4 sk[2][KK];   // [px_in_block][k] = softmax weights for d=0..3

    const int t   = threadIdx.x;
    const int blk = blockIdx.x;
    const int b   = blk / 800;
    const int q   = blk % 800;

    const int wid = t >> 5, lane = t & 31;
    {   // 8 warps = 2 pixels x 4 subpixels
        const int px = wid >> 2, d = wid & 3;
        const int p  = 2 * q + px;
        const int hu = p / 20, pm20 = p % 20;
        const int hc = hu >> 1, sh = hu & 1;
        const int wc = 2 * pm20 + (d >> 1), sw = d & 1;
        float v = -3.0e38f;
        if (lane < KK)
            v = g_kern[((size_t)(b * HH + hc) * WW + wc) * CK + lane * 4 + sh * 2 + sw];
        float m = v;
        #pragma unroll
        for (int off = 16; off; off >>= 1)
            m = fmaxf(m, __shfl_xor_sync(0xffffffffu, m, off));
        float e = (lane < KK) ? __expf(v - m) : 0.f;
        float s = e;
        #pragma unroll
        for (int off = 16; off; off >>= 1)
            s += __shfl_xor_sync(0xffffffffu, s, off);
        if (lane < KK)
            ((float*)&sk[px][lane])[d] = e / s;
    }
    __syncthreads();

    const int half = t >> 7;           // which of the 2 pixels
    const int ch2  = t & 127;          // channel pair index
    const int p    = 2 * q + half;
    const int hsrc = p / WW, wsrc = p % WW;
    const int hu   = p / 20;
    const int wu0  = (p % 20) * 4;

    const float2* xb = (const float2*)
        &g_xT[((size_t)(b * HPAD + hsrc) * HPAD + wsrc) * C_IN + ch2 * 2];
    const ulonglong2* skp = (const ulonglong2*)&sk[half][0];

    u64 a0 = 0, a1 = 0, a2 = 0, a3 = 0;   // {d0,d1},{d2,d3} for ch0 / ch1
    #pragma unroll
    for (int ki = 0; ki < 5; ki++) {
        #pragma unroll
        for (int kj = 0; kj < 5; kj++) {
            float2 xv = xb[(ki * HPAD + kj) * (C_IN / 2)];
            ulonglong2 w = skp[ki * 5 + kj];
            u64 x0 = dup2f(xv.x), x1 = dup2f(xv.y);
            fma2(a0, x0, w.x); fma2(a1, x0, w.y);
            fma2(a2, x1, w.x); fma2(a3, x1, w.y);
        }
    }
    const int ch = ch2 * 2;
    float* d0 = out + ((size_t)(b * C_IN + ch) * (2 * HH) + hu) * (2 * WW) + wu0;
    *(ulonglong2*)d0            = make_ulonglong2(a0, a1);
    *(ulonglong2*)(d0 + 6400)   = make_ulonglong2(a2, a3);   // next channel, same (hu,wu0)
}

// ---------------- launch ----------------
extern "C" void kernel_launch(void* const* d_in, const int* in_sizes, int n_in,
                              void* d_out, int out_size) {
    const float* x     = (const float*)d_in[0];
    const float* wcomp = (const float*)d_in[1];
    const float* wenc  = (const float*)d_in[2];
    float* out = (float*)d_out;

    cudaFuncSetAttribute(stageA_compress,
                         cudaFuncAttributeMaxDynamicSharedMemorySize, SMEM_A_BYTES);
    cudaFuncSetAttribute(stageB_encoder,
                         cudaFuncAttributeMaxDynamicSharedMemorySize, SMEM_B_BYTES);

    stageA_compress<<<100 + (9 * CMID * CK + 255) / 256, 256, SMEM_A_BYTES>>>(x, wcomp, wenc);
    stageB_encoder<<<160, 128, SMEM_B_BYTES>>>();
    stageC_reassemble<<<BATCH * 800, 256>>>(out);
}